// round 5
// baseline (speedup 1.0000x reference)
#include <cuda_runtime.h>
#include <math.h>

// S4D kernel generation:
//   K[h,l] = 2 * Re( sum_n C_scaled[h,n] * exp(dtA[h,n] * l) )
// Per-lane geometric recurrence y *= exp(32*dtA), 2 modes packed per f32x2
// register pair (FFMA2 via PTX), 32 modes per thread, one warp per (h,seg).
// R5: drop nwi array (-32 regs) -- sign-flip yi*wi per iter with a packed
//     XOR on the idle ALU pipe; __launch_bounds__(32,14) so grid=2048 runs
//     as a SINGLE wave (13.8 blocks/SM <= 14 cap). No spills expected.

#define NHALF_C 32
#define NPAIR   16
#define SEGS    4

typedef unsigned long long u64;

#define F2MUL(d,a,b)    asm("mul.rn.f32x2 %0, %1, %2;"     : "=l"(d) : "l"(a), "l"(b))
#define F2FMA(d,a,b,c)  asm("fma.rn.f32x2 %0, %1, %2, %3;" : "=l"(d) : "l"(a), "l"(b), "l"(c))
#define F2ADD(d,a,b)    asm("add.rn.f32x2 %0, %1, %2;"     : "=l"(d) : "l"(a), "l"(b))
#define F2PACK(d,lo,hi) asm("mov.b64 %0, {%1, %2};"        : "=l"(d) : "f"(lo), "f"(hi))
#define F2UNPK(lo,hi,s) asm("mov.b64 {%0, %1}, %2;"        : "=f"(lo), "=f"(hi) : "l"(s))

// Range-reduce x (double) into [-pi, pi], return float residue.
__device__ __forceinline__ float red2pi(double x) {
    const double TWO_PI     = 6.283185307179586476925286766559;
    const double INV_TWO_PI = 0.15915494309189533576888376337251;
    double k = rint(x * INV_TWO_PI);
    return (float)__fma_rn(k, -TWO_PI, x);
}

__global__ void __launch_bounds__(32, 14)
s4d_kernel(const float* __restrict__ C,
           const float* __restrict__ log_dt,
           const float* __restrict__ log_A_real,
           const float* __restrict__ A_imag,
           float* __restrict__ K,
           int H, int L, int iters)
{
    const int blk  = blockIdx.x;
    const int h    = blk / SEGS;
    const int seg  = blk % SEGS;
    const int lane = threadIdx.x;

    const int seg_len = L / SEGS;
    const int l0 = seg * seg_len + lane;

    // dt via double exp (once) so --use_fast_math can't degrade it.
    const float dt = (float)exp((double)log_dt[h]);

    u64 yr[NPAIR], yi[NPAIR], wr[NPAIR], wi[NPAIR];

    #pragma unroll
    for (int p = 0; p < NPAIR; ++p) {
        float yrv[2], yiv[2], wrv[2], wiv[2];
        #pragma unroll
        for (int k = 0; k < 2; ++k) {
            const int n   = 2 * p + k;
            const int idx = h * NHALF_C + n;
            const float arl = log_A_real[idx];
            const float av  = A_imag[idx];
            const float c0  = C[2 * idx + 0];
            const float c1  = C[2 * idx + 1];

            const float are = __expf(arl);               // exp(log_A_real): decay only
            const float dre = -dt * are;                 // Re(dtA)
            const float dim =  dt * av;                  // Im(dtA)

            // w1 = exp(dtA); C_scaled = 2 * C * (w1 - 1) / A, A = (-are, av)
            const float e1 = __expf(dre);
            float s1, co1; __sincosf(dim, &s1, &co1);
            const float numr = __fmaf_rn(e1, co1, -1.0f);
            const float numi = e1 * s1;
            const float tr = c0 * numr - c1 * numi;
            const float ti = c0 * numi + c1 * numr;
            const float inv = 2.0f / (are * are + av * av);
            const float csr = (ti * av - tr * are) * inv;
            const float csi = -(ti * are + tr * av) * inv;

            // y0 = C_scaled * exp(dtA * l0); phase reduced in double
            const float mag = __expf(dre * (float)l0);
            const float ph  = red2pi((double)dim * (double)l0);
            float sp, cp; __sincosf(ph, &sp, &cp);
            const float er = mag * cp, ei = mag * sp;
            yrv[k] = csr * er - csi * ei;
            yiv[k] = csr * ei + csi * er;

            // per-iter multiplier: wstep = exp(32 * dtA)
            const float m32 = __expf(dre * 32.0f);
            const float p32 = red2pi((double)dim * 32.0);
            float s32, c32; __sincosf(p32, &s32, &c32);
            wrv[k] = m32 * c32;
            wiv[k] = m32 * s32;
        }
        F2PACK(yr[p], yrv[0], yrv[1]);
        F2PACK(yi[p], yiv[0], yiv[1]);
        F2PACK(wr[p], wrv[0], wrv[1]);
        F2PACK(wi[p], wiv[0], wiv[1]);
    }

    float* out = K + (size_t)h * L + l0;
    const u64 SGN = 0x8000000080000000ULL;   // packed f32x2 sign-flip mask

    #pragma unroll 2
    for (int it = 0; it < iters; ++it) {
        // ---- reduce current Re(y) across the 16 pairs (packed tree) ----
        u64 t[8];
        #pragma unroll
        for (int j = 0; j < 8; ++j) F2ADD(t[j], yr[2 * j], yr[2 * j + 1]);
        #pragma unroll
        for (int j = 0; j < 4; ++j) F2ADD(t[j], t[2 * j], t[2 * j + 1]);
        #pragma unroll
        for (int j = 0; j < 2; ++j) F2ADD(t[j], t[2 * j], t[2 * j + 1]);
        F2ADD(t[0], t[0], t[1]);

        // ---- advance the recurrence: y *= wstep (uses pre-update yr) ----
        #pragma unroll
        for (int p = 0; p < NPAIR; ++p) {
            u64 m0, m1;
            F2MUL(m0, yi[p], wi[p]);       //  yi*wi
            F2MUL(m1, yr[p], wi[p]);       //  yr*wi (old yr)
            m0 ^= SGN;                     // -yi*wi  (ALU pipe, idle)
            F2FMA(yr[p], yr[p], wr[p], m0);
            F2FMA(yi[p], yi[p], wr[p], m1);
        }

        float a, b; F2UNPK(a, b, t[0]);
        *out = a + b;                       // coalesced 128B/warp store
        out += 32;
    }
}

extern "C" void kernel_launch(void* const* d_in, const int* in_sizes, int n_in,
                              void* d_out, int out_size) {
    const float* C          = (const float*)d_in[0];
    const float* log_dt     = (const float*)d_in[1];
    const float* log_A_real = (const float*)d_in[2];
    const float* A_imag     = (const float*)d_in[3];

    const int H = in_sizes[1];           // log_dt has H elements
    const int L = out_size / H;          // K is (H, L)
    const int iters = L / (SEGS * 32);

    s4d_kernel<<<H * SEGS, 32>>>(C, log_dt, log_A_real, A_imag,
                                 (float*)d_out, H, L, iters);
}

// round 7
// speedup vs baseline: 1.3374x; 1.3374x over previous
#include <cuda_runtime.h>
#include <math.h>

// S4D kernel generation:
//   K[h,l] = 2 * Re( sum_n C_scaled[h,n] * exp(dtA[h,n] * l) )
// Per-lane geometric recurrence y *= exp(32*dtA), 2 modes packed per f32x2
// register pair (FFMA2 via PTX), 32 modes per thread, one warp per (h,seg).
// R7 (= R6 fixed): step multipliers wr/wi/nwi are lane-invariant -> 384B of
//     shared memory, read each iter through a VOLATILE pointer (compiles to
//     broadcast LDS.64 with immediate offset; cannot be hoisted back into
//     registers). Register state ~110-125 -> grid 2048 resident in ONE wave
//     (13.8 blocks/SM). No spills, no wave tail, no block barrier.

#define NHALF_C 32
#define NPAIR   16
#define SEGS    4

typedef unsigned long long u64;

#define F2MUL(d,a,b)    asm("mul.rn.f32x2 %0, %1, %2;"     : "=l"(d) : "l"(a), "l"(b))
#define F2FMA(d,a,b,c)  asm("fma.rn.f32x2 %0, %1, %2, %3;" : "=l"(d) : "l"(a), "l"(b), "l"(c))
#define F2ADD(d,a,b)    asm("add.rn.f32x2 %0, %1, %2;"     : "=l"(d) : "l"(a), "l"(b))
#define F2PACK(d,lo,hi) asm("mov.b64 %0, {%1, %2};"        : "=l"(d) : "f"(lo), "f"(hi))
#define F2UNPK(lo,hi,s) asm("mov.b64 {%0, %1}, %2;"        : "=f"(lo), "=f"(hi) : "l"(s))

// Range-reduce x (double) into [-pi, pi], return float residue.
__device__ __forceinline__ float red2pi(double x) {
    const double TWO_PI     = 6.283185307179586476925286766559;
    const double INV_TWO_PI = 0.15915494309189533576888376337251;
    double k = rint(x * INV_TWO_PI);
    return (float)__fma_rn(k, -TWO_PI, x);
}

__global__ void __launch_bounds__(32, 16)
s4d_kernel(const float* __restrict__ C,
           const float* __restrict__ log_dt,
           const float* __restrict__ log_A_real,
           const float* __restrict__ A_imag,
           float* __restrict__ K,
           int H, int L, int iters)
{
    // layout: [wr(0..15)][wi(0..15)][nwi(0..15)], u64 each
    __shared__ u64 sw[NPAIR * 3];

    const int blk  = blockIdx.x;
    const int h    = blk / SEGS;
    const int seg  = blk % SEGS;
    const int lane = threadIdx.x;

    const int seg_len = L / SEGS;
    const int l0 = seg * seg_len + lane;

    // dt via double exp (once) so --use_fast_math can't degrade it.
    const float dt = (float)exp((double)log_dt[h]);

    u64 yr[NPAIR], yi[NPAIR];

    #pragma unroll
    for (int p = 0; p < NPAIR; ++p) {
        float yrv[2], yiv[2], wrv[2], wiv[2];
        #pragma unroll
        for (int k = 0; k < 2; ++k) {
            const int n   = 2 * p + k;
            const int idx = h * NHALF_C + n;
            const float arl = log_A_real[idx];
            const float av  = A_imag[idx];
            const float c0  = C[2 * idx + 0];
            const float c1  = C[2 * idx + 1];

            const float are = __expf(arl);               // exp(log_A_real): decay only
            const float dre = -dt * are;                 // Re(dtA)
            const float dim =  dt * av;                  // Im(dtA)

            // w1 = exp(dtA); C_scaled = 2 * C * (w1 - 1) / A, A = (-are, av)
            const float e1 = __expf(dre);
            float s1, co1; __sincosf(dim, &s1, &co1);
            const float numr = __fmaf_rn(e1, co1, -1.0f);
            const float numi = e1 * s1;
            const float tr = c0 * numr - c1 * numi;
            const float ti = c0 * numi + c1 * numr;
            const float inv = 2.0f / (are * are + av * av);
            const float csr = (ti * av - tr * are) * inv;
            const float csi = -(ti * are + tr * av) * inv;

            // y0 = C_scaled * exp(dtA * l0); phase reduced in double
            const float mag = __expf(dre * (float)l0);
            const float ph  = red2pi((double)dim * (double)l0);
            float sp, cp; __sincosf(ph, &sp, &cp);
            const float er = mag * cp, ei = mag * sp;
            yrv[k] = csr * er - csi * ei;
            yiv[k] = csr * ei + csi * er;

            // per-iter multiplier: wstep = exp(32 * dtA)
            const float m32 = __expf(dre * 32.0f);
            const float p32 = red2pi((double)dim * 32.0);
            float s32, c32; __sincosf(p32, &s32, &c32);
            wrv[k] = m32 * c32;
            wiv[k] = m32 * s32;
        }
        F2PACK(yr[p], yrv[0], yrv[1]);
        F2PACK(yi[p], yiv[0], yiv[1]);

        if (lane == 0) {                 // lane-invariant: one writer
            u64 w0, w1, w2;
            F2PACK(w0,  wrv[0],  wrv[1]);
            F2PACK(w1,  wiv[0],  wiv[1]);
            F2PACK(w2, -wiv[0], -wiv[1]);
            sw[p]             = w0;
            sw[NPAIR + p]     = w1;
            sw[2 * NPAIR + p] = w2;
        }
    }
    __syncthreads();   // single-warp block: cheap; drains the STS

    // Volatile view: forces LDS each iteration (no register promotion).
    volatile const u64* swv = sw;

    float* out = K + (size_t)h * L + l0;

    #pragma unroll 2
    for (int it = 0; it < iters; ++it) {
        // ---- reduce current Re(y) across the 16 pairs (packed tree) ----
        u64 t[8];
        #pragma unroll
        for (int j = 0; j < 8; ++j) F2ADD(t[j], yr[2 * j], yr[2 * j + 1]);
        #pragma unroll
        for (int j = 0; j < 4; ++j) F2ADD(t[j], t[2 * j], t[2 * j + 1]);
        #pragma unroll
        for (int j = 0; j < 2; ++j) F2ADD(t[j], t[2 * j], t[2 * j + 1]);
        F2ADD(t[0], t[0], t[1]);

        // ---- advance the recurrence: y *= wstep (w from smem broadcast) ----
        #pragma unroll
        for (int p = 0; p < NPAIR; ++p) {
            u64 wrv  = swv[p];
            u64 wiv  = swv[NPAIR + p];
            u64 nwiv = swv[2 * NPAIR + p];
            u64 m0, m1;
            F2MUL(m0, yi[p], nwiv);        // -yi*wi
            F2MUL(m1, yr[p], wiv);         //  yr*wi (old yr)
            F2FMA(yr[p], yr[p], wrv, m0);
            F2FMA(yi[p], yi[p], wrv, m1);
        }

        float a, b; F2UNPK(a, b, t[0]);
        *out = a + b;                       // coalesced 128B/warp store
        out += 32;
    }
}

extern "C" void kernel_launch(void* const* d_in, const int* in_sizes, int n_in,
                              void* d_out, int out_size) {
    const float* C          = (const float*)d_in[0];
    const float* log_dt     = (const float*)d_in[1];
    const float* log_A_real = (const float*)d_in[2];
    const float* A_imag     = (const float*)d_in[3];

    const int H = in_sizes[1];           // log_dt has H elements
    const int L = out_size / H;          // K is (H, L)
    const int iters = L / (SEGS * 32);

    s4d_kernel<<<H * SEGS, 32>>>(C, log_dt, log_A_real, A_imag,
                                 (float*)d_out, H, L, iters);
}

// round 8
// speedup vs baseline: 1.4593x; 1.0912x over previous
#include <cuda_runtime.h>
#include <math.h>

// S4D kernel generation:
//   K[h,l] = 2 * Re( sum_n C_scaled[h,n] * exp(dtA[h,n] * l) )
// R8: lane-split modes. Lane i owns l = l0+(i>>1) and mode half (i&1):
//     8 f32x2 pairs of state per thread (~32 regs of y). Warp emits 16
//     outputs/iter via shfl.bfly(1) combine. Step multiplier exp(16*dtA)
//     lives in smem (volatile broadcast LDS, per half). SEGS=8 -> grid
//     4096, launch_bounds(32,28) -> ~27.7 blocks/SM in ONE wave.

#define NHALF_C 32
#define NPAIR   8      // pairs per thread (16 modes; the other 16 in the buddy lane)
#define SEGS    8
#define LSTEP   16     // l advance per iteration (16 l per warp-iter)

typedef unsigned long long u64;

#define F2MUL(d,a,b)    asm("mul.rn.f32x2 %0, %1, %2;"     : "=l"(d) : "l"(a), "l"(b))
#define F2FMA(d,a,b,c)  asm("fma.rn.f32x2 %0, %1, %2, %3;" : "=l"(d) : "l"(a), "l"(b), "l"(c))
#define F2ADD(d,a,b)    asm("add.rn.f32x2 %0, %1, %2;"     : "=l"(d) : "l"(a), "l"(b))
#define F2PACK(d,lo,hi) asm("mov.b64 %0, {%1, %2};"        : "=l"(d) : "f"(lo), "f"(hi))
#define F2UNPK(lo,hi,s) asm("mov.b64 {%0, %1}, %2;"        : "=f"(lo), "=f"(hi) : "l"(s))

// Range-reduce x (double) into [-pi, pi], return float residue.
__device__ __forceinline__ float red2pi(double x) {
    const double TWO_PI     = 6.283185307179586476925286766559;
    const double INV_TWO_PI = 0.15915494309189533576888376337251;
    double k = rint(x * INV_TWO_PI);
    return (float)__fma_rn(k, -TWO_PI, x);
}

__global__ void __launch_bounds__(32, 28)
s4d_kernel(const float* __restrict__ C,
           const float* __restrict__ log_dt,
           const float* __restrict__ log_A_real,
           const float* __restrict__ A_imag,
           float* __restrict__ K,
           int H, int L, int iters)
{
    // [half][wr|wi|nwi][pair], u64 each = 384 B
    __shared__ u64 sw[2][3][NPAIR];

    const int blk   = blockIdx.x;
    const int h     = blk / SEGS;
    const int seg   = blk % SEGS;
    const int lane  = threadIdx.x;
    const int lhalf = lane >> 1;     // which l within the 16-wide group
    const int half  = lane & 1;      // which 16-mode half this lane owns

    const int seg_len = L / SEGS;
    const int l0 = seg * seg_len + lhalf;

    // dt via double exp (once) so --use_fast_math can't degrade it.
    const float dt = (float)exp((double)log_dt[h]);

    u64 yr[NPAIR], yi[NPAIR];

    #pragma unroll
    for (int p = 0; p < NPAIR; ++p) {
        float yrv[2], yiv[2], wrv[2], wiv[2];
        #pragma unroll
        for (int k = 0; k < 2; ++k) {
            const int n   = half * 16 + 2 * p + k;
            const int idx = h * NHALF_C + n;
            const float arl = log_A_real[idx];
            const float av  = A_imag[idx];
            const float c0  = C[2 * idx + 0];
            const float c1  = C[2 * idx + 1];

            const float are = __expf(arl);               // exp(log_A_real): decay only
            const float dre = -dt * are;                 // Re(dtA)
            const float dim =  dt * av;                  // Im(dtA)

            // w1 = exp(dtA); C_scaled = 2 * C * (w1 - 1) / A, A = (-are, av)
            const float e1 = __expf(dre);
            float s1, co1; __sincosf(dim, &s1, &co1);
            const float numr = __fmaf_rn(e1, co1, -1.0f);
            const float numi = e1 * s1;
            const float tr = c0 * numr - c1 * numi;
            const float ti = c0 * numi + c1 * numr;
            const float inv = 2.0f / (are * are + av * av);
            const float csr = (ti * av - tr * are) * inv;
            const float csi = -(ti * are + tr * av) * inv;

            // y0 = C_scaled * exp(dtA * l0); phase reduced in double
            const float mag = __expf(dre * (float)l0);
            const float ph  = red2pi((double)dim * (double)l0);
            float sp, cp; __sincosf(ph, &sp, &cp);
            const float er = mag * cp, ei = mag * sp;
            yrv[k] = csr * er - csi * ei;
            yiv[k] = csr * ei + csi * er;

            // per-iter multiplier: wstep = exp(LSTEP * dtA)
            const float m16 = __expf(dre * (float)LSTEP);
            const float p16 = red2pi((double)dim * (double)LSTEP);
            float s16, c16; __sincosf(p16, &s16, &c16);
            wrv[k] = m16 * c16;
            wiv[k] = m16 * s16;
        }
        F2PACK(yr[p], yrv[0], yrv[1]);
        F2PACK(yi[p], yiv[0], yiv[1]);

        if (lhalf == 0) {                // one writer per half (lanes 0 and 1)
            u64 w0, w1, w2;
            F2PACK(w0,  wrv[0],  wrv[1]);
            F2PACK(w1,  wiv[0],  wiv[1]);
            F2PACK(w2, -wiv[0], -wiv[1]);
            sw[half][0][p] = w0;
            sw[half][1][p] = w1;
            sw[half][2][p] = w2;
        }
    }
    __syncwarp();   // single-warp block: drains the STS, orders smem

    // Volatile view (per-half base): forces broadcast LDS each iteration.
    volatile const u64* swv = &sw[half][0][0];

    float* out = K + (size_t)h * L + seg * seg_len + lhalf;

    #pragma unroll 2
    for (int it = 0; it < iters; ++it) {
        // ---- reduce current Re(y) across this lane's 8 pairs ----
        u64 t[4];
        #pragma unroll
        for (int j = 0; j < 4; ++j) F2ADD(t[j], yr[2 * j], yr[2 * j + 1]);
        F2ADD(t[0], t[0], t[1]);
        F2ADD(t[2], t[2], t[3]);
        F2ADD(t[0], t[0], t[2]);
        float a, b; F2UNPK(a, b, t[0]);
        const float part = a + b;

        // combine the two mode-halves living in buddy lanes
        const float tot = part + __shfl_xor_sync(0xffffffffu, part, 1);

        // ---- advance the recurrence: y *= wstep (w from smem broadcast) ----
        #pragma unroll
        for (int p = 0; p < NPAIR; ++p) {
            u64 wrv  = swv[p];
            u64 wiv  = swv[NPAIR + p];
            u64 nwiv = swv[2 * NPAIR + p];
            u64 m0, m1;
            F2MUL(m0, yi[p], nwiv);        // -yi*wi
            F2MUL(m1, yr[p], wiv);         //  yr*wi (old yr)
            F2FMA(yr[p], yr[p], wrv, m0);
            F2FMA(yi[p], yi[p], wrv, m1);
        }

        if (half == 0) *out = tot;         // 16 lanes, 64B coalesced
        out += LSTEP;
    }
}

extern "C" void kernel_launch(void* const* d_in, const int* in_sizes, int n_in,
                              void* d_out, int out_size) {
    const float* C          = (const float*)d_in[0];
    const float* log_dt     = (const float*)d_in[1];
    const float* log_A_real = (const float*)d_in[2];
    const float* A_imag     = (const float*)d_in[3];

    const int H = in_sizes[1];           // log_dt has H elements
    const int L = out_size / H;          // K is (H, L)
    const int iters = L / (SEGS * LSTEP);

    s4d_kernel<<<H * SEGS, 32>>>(C, log_dt, log_A_real, A_imag,
                                 (float*)d_out, H, L, iters);
}

// round 9
// speedup vs baseline: 1.5358x; 1.0524x over previous
#include <cuda_runtime.h>
#include <math.h>

// S4D kernel generation:
//   K[h,l] = 2 * Re( sum_n C_scaled[h,n] * exp(dtA[h,n] * l) )
// R9 (on R8's lane-split layout): state stored as (yr, v=-yi) so the
//   rotation needs no negation ops; step constants (wr, wi, swi=-wi) in
//   smem read as vectorized LDS.128 (ld.shared.v2.u64, asm volatile) --
//   12 LDS/iter instead of 24 LDS.64, cutting the crossbar tax ~3x.
//   SEGS=8, launch_bounds(32,28): grid 4096 in one wave, ~7 warps/SMSP.

#define NHALF_C 32
#define NPAIR   8      // f32x2 pairs per thread (16 modes; buddy lane has rest)
#define SEGS    8
#define LSTEP   16     // l advance per iteration (16 l per warp-iter)

typedef unsigned long long u64;

#define F2MUL(d,a,b)    asm("mul.rn.f32x2 %0, %1, %2;"     : "=l"(d) : "l"(a), "l"(b))
#define F2FMA(d,a,b,c)  asm("fma.rn.f32x2 %0, %1, %2, %3;" : "=l"(d) : "l"(a), "l"(b), "l"(c))
#define F2ADD(d,a,b)    asm("add.rn.f32x2 %0, %1, %2;"     : "=l"(d) : "l"(a), "l"(b))
#define F2PACK(d,lo,hi) asm("mov.b64 %0, {%1, %2};"        : "=l"(d) : "f"(lo), "f"(hi))
#define F2UNPK(lo,hi,s) asm("mov.b64 {%0, %1}, %2;"        : "=f"(lo), "=f"(hi) : "l"(s))

// Un-hoistable vector LDS: two u64 from [addr] (16B aligned).
#define LDSV2(d0, d1, addr) \
    asm volatile("ld.shared.v2.u64 {%0, %1}, [%2];" \
                 : "=l"(d0), "=l"(d1) : "r"(addr))

// Range-reduce x (double) into [-pi, pi], return float residue.
__device__ __forceinline__ float red2pi(double x) {
    const double TWO_PI     = 6.283185307179586476925286766559;
    const double INV_TWO_PI = 0.15915494309189533576888376337251;
    double k = rint(x * INV_TWO_PI);
    return (float)__fma_rn(k, -TWO_PI, x);
}

__global__ void __launch_bounds__(32, 28)
s4d_kernel(const float* __restrict__ C,
           const float* __restrict__ log_dt,
           const float* __restrict__ log_A_real,
           const float* __restrict__ A_imag,
           float* __restrict__ K,
           int H, int L, int iters)
{
    // [half][wr(8) | wi(8) | swi(8)] u64 each, 16B-aligned for LDS.128
    __shared__ __align__(16) u64 sw[2][3][NPAIR];

    const int blk   = blockIdx.x;
    const int h     = blk / SEGS;
    const int seg   = blk % SEGS;
    const int lane  = threadIdx.x;
    const int lhalf = lane >> 1;     // which l within the 16-wide group
    const int half  = lane & 1;      // which 16-mode half this lane owns

    const int seg_len = L / SEGS;
    const int l0 = seg * seg_len + lhalf;

    // dt via double exp (once) so --use_fast_math can't degrade it.
    const float dt = (float)exp((double)log_dt[h]);

    u64 yr[NPAIR], yv[NPAIR];        // yv holds v = -yi

    #pragma unroll
    for (int p = 0; p < NPAIR; ++p) {
        float yrv[2], yvv[2], wrv[2], wiv[2];
        #pragma unroll
        for (int k = 0; k < 2; ++k) {
            const int n   = half * 16 + 2 * p + k;
            const int idx = h * NHALF_C + n;
            const float arl = log_A_real[idx];
            const float av  = A_imag[idx];
            const float c0  = C[2 * idx + 0];
            const float c1  = C[2 * idx + 1];

            const float are = __expf(arl);               // exp(log_A_real): decay only
            const float dre = -dt * are;                 // Re(dtA)
            const float dim =  dt * av;                  // Im(dtA)

            // w1 = exp(dtA); C_scaled = 2 * C * (w1 - 1) / A, A = (-are, av)
            const float e1 = __expf(dre);
            float s1, co1; __sincosf(dim, &s1, &co1);
            const float numr = __fmaf_rn(e1, co1, -1.0f);
            const float numi = e1 * s1;
            const float tr = c0 * numr - c1 * numi;
            const float ti = c0 * numi + c1 * numr;
            const float inv = 2.0f / (are * are + av * av);
            const float csr = (ti * av - tr * are) * inv;
            const float csi = -(ti * are + tr * av) * inv;

            // y0 = C_scaled * exp(dtA * l0); phase reduced in double
            const float mag = __expf(dre * (float)l0);
            const float ph  = red2pi((double)dim * (double)l0);
            float sp, cp; __sincosf(ph, &sp, &cp);
            const float er = mag * cp, ei = mag * sp;
            yrv[k] =   csr * er - csi * ei;
            yvv[k] = -(csr * ei + csi * er);             // v = -Im(y)

            // per-iter multiplier: wstep = exp(LSTEP * dtA)
            const float m16 = __expf(dre * (float)LSTEP);
            const float p16 = red2pi((double)dim * (double)LSTEP);
            float s16, c16; __sincosf(p16, &s16, &c16);
            wrv[k] = m16 * c16;
            wiv[k] = m16 * s16;
        }
        F2PACK(yr[p], yrv[0], yrv[1]);
        F2PACK(yv[p], yvv[0], yvv[1]);

        if (lhalf == 0) {                // one writer per half (lanes 0 and 1)
            u64 w0, w1, w2;
            F2PACK(w0,  wrv[0],  wrv[1]);
            F2PACK(w1,  wiv[0],  wiv[1]);
            F2PACK(w2, -wiv[0], -wiv[1]);
            sw[half][0][p] = w0;         // wr
            sw[half][1][p] = w1;         // wi
            sw[half][2][p] = w2;         // swi = -wi
        }
    }
    __syncwarp();   // single-warp block: drains the STS, orders smem

    unsigned swb;
    asm("{ .reg .u64 t; cvta.to.shared.u64 t, %1; cvt.u32.u64 %0, t; }"
        : "=r"(swb) : "l"(&sw[half][0][0]));

    float* out = K + (size_t)h * L + seg * seg_len + lhalf;

    #pragma unroll 2
    for (int it = 0; it < iters; ++it) {
        // ---- reduce current Re(y) across this lane's 8 pairs ----
        u64 t[4];
        #pragma unroll
        for (int j = 0; j < 4; ++j) F2ADD(t[j], yr[2 * j], yr[2 * j + 1]);
        F2ADD(t[0], t[0], t[1]);
        F2ADD(t[2], t[2], t[3]);
        F2ADD(t[0], t[0], t[2]);
        float a, b; F2UNPK(a, b, t[0]);
        const float part = a + b;

        // combine the two mode-halves living in buddy lanes
        const float tot = part + __shfl_xor_sync(0xffffffffu, part, 1);

        // ---- advance: y *= wstep; constants via vectorized broadcast LDS ----
        #pragma unroll
        for (int j = 0; j < 4; ++j) {            // 2 pairs per group
            u64 wr0, wr1, wi0, wi1, sw0, sw1;
            LDSV2(wr0, wr1, swb +       16 * j); // wr[2j], wr[2j+1]
            LDSV2(wi0, wi1, swb +  64 + 16 * j); // wi
            LDSV2(sw0, sw1, swb + 128 + 16 * j); // swi
            u64 m0, m1;
            const int p0 = 2 * j, p1 = 2 * j + 1;
            F2MUL(m0, yv[p0], wi0);              //  v*wi
            F2MUL(m1, yr[p0], sw0);              //  yr*(-wi)
            F2FMA(yr[p0], yr[p0], wr0, m0);      // yr*wr - yi*wi
            F2FMA(yv[p0], yv[p0], wr0, m1);      // -(yi*wr + yr*wi)
            F2MUL(m0, yv[p1], wi1);
            F2MUL(m1, yr[p1], sw1);
            F2FMA(yr[p1], yr[p1], wr1, m0);
            F2FMA(yv[p1], yv[p1], wr1, m1);
        }

        if (half == 0) *out = tot;               // 16 lanes, 64B coalesced
        out += LSTEP;
    }
}

extern "C" void kernel_launch(void* const* d_in, const int* in_sizes, int n_in,
                              void* d_out, int out_size) {
    const float* C          = (const float*)d_in[0];
    const float* log_dt     = (const float*)d_in[1];
    const float* log_A_real = (const float*)d_in[2];
    const float* A_imag     = (const float*)d_in[3];

    const int H = in_sizes[1];           // log_dt has H elements
    const int L = out_size / H;          // K is (H, L)
    const int iters = L / (SEGS * LSTEP);

    s4d_kernel<<<H * SEGS, 32>>>(C, log_dt, log_A_real, A_imag,
                                 (float*)d_out, H, L, iters);
}

// round 10
// speedup vs baseline: 1.6651x; 1.0842x over previous
#include <cuda_runtime.h>
#include <math.h>

// S4D kernel generation:
//   K[h,l] = 2 * Re( sum_n C_scaled[h,n] * exp(dtA[h,n] * l) )
// R10: second-order REAL recurrence. x = Re(y) obeys
//        x(l+s) = a*x(l) - b*x(l-s),  a = 2*Re(w), b = |w|^2, w = exp(s*dtA)
//      -> 2 packed fma-ops per mode-pair per step (was 4), no imag state
//      rotation. Ping-pong (xc, xo) buffers; constants (a, -b) in smem via
//      un-hoistable LDS.128. Lane-split layout from R8/R9: lane = (l, half),
//      shfl.bfly(1) combine, SEGS=8, grid 4096, one wave (~28 blocks/SM).

#define NHALF_C 32
#define NPAIR   8      // f32x2 pairs per thread (16 modes; buddy lane has rest)
#define SEGS    8
#define LSTEP   16     // l advance per iteration (16 l per warp-iter)

typedef unsigned long long u64;

#define F2MUL(d,a,b)    asm("mul.rn.f32x2 %0, %1, %2;"     : "=l"(d) : "l"(a), "l"(b))
#define F2FMA(d,a,b,c)  asm("fma.rn.f32x2 %0, %1, %2, %3;" : "=l"(d) : "l"(a), "l"(b), "l"(c))
#define F2ADD(d,a,b)    asm("add.rn.f32x2 %0, %1, %2;"     : "=l"(d) : "l"(a), "l"(b))
#define F2PACK(d,lo,hi) asm("mov.b64 %0, {%1, %2};"        : "=l"(d) : "f"(lo), "f"(hi))
#define F2UNPK(lo,hi,s) asm("mov.b64 {%0, %1}, %2;"        : "=f"(lo), "=f"(hi) : "l"(s))

// Un-hoistable vector LDS: two u64 from [addr] (16B aligned).
#define LDSV2(d0, d1, addr) \
    asm volatile("ld.shared.v2.u64 {%0, %1}, [%2];" \
                 : "=l"(d0), "=l"(d1) : "r"(addr))

// Range-reduce x (double) into [-pi, pi], return float residue.
__device__ __forceinline__ float red2pi(double x) {
    const double TWO_PI     = 6.283185307179586476925286766559;
    const double INV_TWO_PI = 0.15915494309189533576888376337251;
    double k = rint(x * INV_TWO_PI);
    return (float)__fma_rn(k, -TWO_PI, x);
}

// One recurrence step + output for the current buffer.
//   cur  : x(l)        (read, reduced, then overwritten location = old)
//   old  : x(l-LSTEP)  (overwritten with x(l+LSTEP))
#define BODY(cur, old)                                                     \
    do {                                                                   \
        u64 t0, t1, t2, t3;                                                \
        F2ADD(t0, cur[0], cur[1]);                                         \
        F2ADD(t1, cur[2], cur[3]);                                         \
        F2ADD(t2, cur[4], cur[5]);                                         \
        F2ADD(t3, cur[6], cur[7]);                                         \
        F2ADD(t0, t0, t1);                                                 \
        F2ADD(t2, t2, t3);                                                 \
        F2ADD(t0, t0, t2);                                                 \
        float ra, rb; F2UNPK(ra, rb, t0);                                  \
        const float part = ra + rb;                                        \
        const float tot = part + __shfl_xor_sync(0xffffffffu, part, 1);    \
        _Pragma("unroll")                                                  \
        for (int j = 0; j < 4; ++j) {                                      \
            u64 a0, a1, nb0, nb1, m0, m1;                                  \
            LDSV2(a0,  a1,  swb +      16 * j);                            \
            LDSV2(nb0, nb1, swb + 64 + 16 * j);                            \
            const int p0 = 2 * j, p1 = 2 * j + 1;                          \
            F2MUL(m0, old[p0], nb0);            /* -b*x(l-s) */            \
            F2MUL(m1, old[p1], nb1);                                       \
            F2FMA(old[p0], cur[p0], a0, m0);    /* a*x(l) - b*x(l-s) */    \
            F2FMA(old[p1], cur[p1], a1, m1);                               \
        }                                                                  \
        if (half == 0) *out = tot;              /* 16 lanes, 64B store */  \
        out += LSTEP;                                                      \
    } while (0)

__global__ void __launch_bounds__(32, 28)
s4d_kernel(const float* __restrict__ C,
           const float* __restrict__ log_dt,
           const float* __restrict__ log_A_real,
           const float* __restrict__ A_imag,
           float* __restrict__ K,
           int H, int L, int iters)
{
    // [half][a(8) | nb(8)] u64 each, 16B-aligned for LDS.128 (256 B total)
    __shared__ __align__(16) u64 sw[2][2][NPAIR];

    const int blk   = blockIdx.x;
    const int h     = blk / SEGS;
    const int seg   = blk % SEGS;
    const int lane  = threadIdx.x;
    const int lhalf = lane >> 1;     // which l within the 16-wide group
    const int half  = lane & 1;      // which 16-mode half this lane owns

    const int seg_len = L / SEGS;
    const int l0 = seg * seg_len + lhalf;

    // dt via double exp (once) so --use_fast_math can't degrade it.
    const float dt = (float)exp((double)log_dt[h]);

    u64 xc[NPAIR], xo[NPAIR];        // x(l0), x(l0 - LSTEP)

    #pragma unroll
    for (int p = 0; p < NPAIR; ++p) {
        float xcv[2], xov[2], av[2], nbv[2];
        #pragma unroll
        for (int k = 0; k < 2; ++k) {
            const int n   = half * 16 + 2 * p + k;
            const int idx = h * NHALF_C + n;
            const float arl = log_A_real[idx];
            const float aim = A_imag[idx];
            const float c0  = C[2 * idx + 0];
            const float c1  = C[2 * idx + 1];

            const float are = __expf(arl);               // exp(log_A_real): decay only
            const float dre = -dt * are;                 // Re(dtA)
            const float dim =  dt * aim;                 // Im(dtA)

            // w1 = exp(dtA); C_scaled = 2 * C * (w1 - 1) / A, A = (-are, aim)
            const float e1 = __expf(dre);
            float s1, co1; __sincosf(dim, &s1, &co1);
            const float numr = __fmaf_rn(e1, co1, -1.0f);
            const float numi = e1 * s1;
            const float tr = c0 * numr - c1 * numi;
            const float ti = c0 * numi + c1 * numr;
            const float inv = 2.0f / (are * are + aim * aim);
            const float csr = (ti * aim - tr * are) * inv;
            const float csi = -(ti * are + tr * aim) * inv;

            // y0 = C_scaled * exp(dtA * l0); phase reduced in double
            const float mag = __expf(dre * (float)l0);
            const float ph  = red2pi((double)dim * (double)l0);
            float sp, cp; __sincosf(ph, &sp, &cp);
            const float er = mag * cp, ei = mag * sp;
            const float yr0 = csr * er - csi * ei;
            const float yi0 = csr * ei + csi * er;

            // step multiplier w = exp(LSTEP * dtA)
            const float m16 = __expf(dre * (float)LSTEP);
            const float p16 = red2pi((double)dim * (double)LSTEP);
            float s16, c16; __sincosf(p16, &s16, &c16);
            const float wr = m16 * c16;
            const float wi = m16 * s16;

            const float b   = __fmaf_rn(wr, wr, wi * wi);   // |w|^2
            av[k]  = 2.0f * wr;                              // a = 2 Re(w)
            nbv[k] = -b;
            xcv[k] = yr0;                                    // x(l0)
            // x(l0 - LSTEP) = Re(y0 * conj(w)) / |w|^2
            xov[k] = __fmaf_rn(yr0, wr, yi0 * wi) / b;
        }
        F2PACK(xc[p], xcv[0], xcv[1]);
        F2PACK(xo[p], xov[0], xov[1]);

        if (lhalf == 0) {                // one writer per half (lanes 0 and 1)
            u64 w0, w1;
            F2PACK(w0, av[0],  av[1]);
            F2PACK(w1, nbv[0], nbv[1]);
            sw[half][0][p] = w0;         // a
            sw[half][1][p] = w1;         // -b
        }
    }
    __syncwarp();   // single-warp block: drains the STS, orders smem

    unsigned swb;
    asm("{ .reg .u64 t; cvta.to.shared.u64 t, %1; cvt.u32.u64 %0, t; }"
        : "=r"(swb) : "l"(&sw[half][0][0]));

    float* out = K + (size_t)h * L + seg * seg_len + lhalf;

    // iters is even (64): ping-pong the two buffers, no register copies.
    #pragma unroll 1
    for (int it = 0; it < iters; it += 2) {
        BODY(xc, xo);   // outputs x(l), xo <- x(l+LSTEP)
        BODY(xo, xc);   // outputs x(l+LSTEP), xc <- x(l+2*LSTEP)
    }
}

extern "C" void kernel_launch(void* const* d_in, const int* in_sizes, int n_in,
                              void* d_out, int out_size) {
    const float* C          = (const float*)d_in[0];
    const float* log_dt     = (const float*)d_in[1];
    const float* log_A_real = (const float*)d_in[2];
    const float* A_imag     = (const float*)d_in[3];

    const int H = in_sizes[1];           // log_dt has H elements
    const int L = out_size / H;          // K is (H, L)
    const int iters = L / (SEGS * LSTEP);

    s4d_kernel<<<H * SEGS, 32>>>(C, log_dt, log_A_real, A_imag,
                                 (float*)d_out, H, L, iters);
}

// round 11
// speedup vs baseline: 3.8657x; 2.3216x over previous
#include <cuda_runtime.h>
#include <math.h>

// S4D kernel generation:
//   K[h,l] = 2 * Re( sum_n C_scaled[h,n] * exp(dtA[h,n] * l) )
// Main loop (R10): second-order real recurrence x(l+s) = a*x(l) - b*x(l-s),
//   2 packed fma-ops per mode-pair per step, constants via LDS.128.
// R11: lane-parallel init. Lane n computes mode n's invariants in ONE pass
//   (csr,csi,dre,dim,wr,wi,a,-b,invb,phase_base) -> smem staging. fp64 cut
//   from ~96 ops/thread to 3 (one red2pi) + one double exp for dt. Per-mode
//   thread loop is then LDS.128 + float Cody-Waite phase + expf + sincosf.

#define NHALF_C 32
#define NPAIR   8      // f32x2 pairs per thread (16 modes; buddy lane has rest)
#define SEGS    8
#define LSTEP   16     // l advance per iteration (16 l per warp-iter)

typedef unsigned long long u64;

#define F2MUL(d,a,b)    asm("mul.rn.f32x2 %0, %1, %2;"     : "=l"(d) : "l"(a), "l"(b))
#define F2FMA(d,a,b,c)  asm("fma.rn.f32x2 %0, %1, %2, %3;" : "=l"(d) : "l"(a), "l"(b), "l"(c))
#define F2ADD(d,a,b)    asm("add.rn.f32x2 %0, %1, %2;"     : "=l"(d) : "l"(a), "l"(b))
#define F2PACK(d,lo,hi) asm("mov.b64 %0, {%1, %2};"        : "=l"(d) : "f"(lo), "f"(hi))
#define F2UNPK(lo,hi,s) asm("mov.b64 {%0, %1}, %2;"        : "=f"(lo), "=f"(hi) : "l"(s))

// Un-hoistable vector LDS: two u64 from [addr] (16B aligned).
#define LDSV2(d0, d1, addr) \
    asm volatile("ld.shared.v2.u64 {%0, %1}, [%2];" \
                 : "=l"(d0), "=l"(d1) : "r"(addr))

// Range-reduce x (double) into [-pi, pi], return float residue.
__device__ __forceinline__ float red2pi(double x) {
    const double TWO_PI     = 6.283185307179586476925286766559;
    const double INV_TWO_PI = 0.15915494309189533576888376337251;
    double k = rint(x * INV_TWO_PI);
    return (float)__fma_rn(k, -TWO_PI, x);
}

// Float Cody-Waite reduce: s in [-4, ~160] -> [-pi, pi].
// HI = 6.28125 (8-bit mantissa; exact times k<=26), MID carries the rest.
__device__ __forceinline__ float red2pi_f(float s) {
    const float INV2PI  = 0.15915494309189533f;
    const float PI2_HI  = 6.28125f;
    const float PI2_MID = 1.9353071786565706e-3f;   // 2*pi - 6.28125
    float k = rintf(s * INV2PI);
    float r = __fmaf_rn(k, -PI2_HI, s);
    return __fmaf_rn(k, -PI2_MID, r);
}

// One recurrence step + output for the current buffer.
#define BODY(cur, old)                                                     \
    do {                                                                   \
        u64 t0, t1, t2, t3;                                                \
        F2ADD(t0, cur[0], cur[1]);                                         \
        F2ADD(t1, cur[2], cur[3]);                                         \
        F2ADD(t2, cur[4], cur[5]);                                         \
        F2ADD(t3, cur[6], cur[7]);                                         \
        F2ADD(t0, t0, t1);                                                 \
        F2ADD(t2, t2, t3);                                                 \
        F2ADD(t0, t0, t2);                                                 \
        float ra, rb; F2UNPK(ra, rb, t0);                                  \
        const float part = ra + rb;                                        \
        const float tot = part + __shfl_xor_sync(0xffffffffu, part, 1);    \
        _Pragma("unroll")                                                  \
        for (int j = 0; j < 4; ++j) {                                      \
            u64 a0, a1, nb0, nb1, m0, m1;                                  \
            LDSV2(a0,  a1,  swb +      16 * j);                            \
            LDSV2(nb0, nb1, swb + 64 + 16 * j);                            \
            const int p0 = 2 * j, p1 = 2 * j + 1;                          \
            F2MUL(m0, old[p0], nb0);            /* -b*x(l-s) */            \
            F2MUL(m1, old[p1], nb1);                                       \
            F2FMA(old[p0], cur[p0], a0, m0);    /* a*x(l) - b*x(l-s) */    \
            F2FMA(old[p1], cur[p1], a1, m1);                               \
        }                                                                  \
        if (half == 0) *out = tot;              /* 16 lanes, 64B store */  \
        out += LSTEP;                                                      \
    } while (0)

__global__ void __launch_bounds__(32, 28)
s4d_kernel(const float* __restrict__ C,
           const float* __restrict__ log_dt,
           const float* __restrict__ log_A_real,
           const float* __restrict__ A_imag,
           float* __restrict__ K,
           int H, int L, int iters)
{
    // recurrence constants: [half][a(16 floats) | nb(16 floats)] = 256 B
    __shared__ __align__(16) float swc[2][2][16];
    // staging: per mode n, two float4s
    __shared__ __align__(16) float4 stA[NHALF_C];   // {csr, csi, dre, dim}
    __shared__ __align__(16) float4 stB[NHALF_C];   // {phase_base, wr, wi, invb}

    const int blk   = blockIdx.x;
    const int h     = blk / SEGS;
    const int seg   = blk % SEGS;
    const int lane  = threadIdx.x;
    const int lhalf = lane >> 1;     // which l within the 16-wide group
    const int half  = lane & 1;      // which 16-mode half this lane owns

    const int seg_len = L / SEGS;
    const int l_base  = seg * seg_len;
    const int l0      = l_base + lhalf;

    // dt via double exp (once) so --use_fast_math can't degrade it.
    const float dt = (float)exp((double)log_dt[h]);

    // ---------- Phase A: lane n computes mode n's invariants ----------
    {
        const int n   = lane;
        const int idx = h * NHALF_C + n;
        const float arl = log_A_real[idx];
        const float aim = A_imag[idx];
        const float c0  = C[2 * idx + 0];
        const float c1  = C[2 * idx + 1];

        const float are = __expf(arl);               // exp(log_A_real)
        const float dre = -dt * are;                 // Re(dtA)
        const float dim =  dt * aim;                 // Im(dtA)

        // w1 = exp(dtA); C_scaled = 2 * C * (w1 - 1) / A, A = (-are, aim)
        const float e1 = __expf(dre);
        float s1, co1; __sincosf(dim, &s1, &co1);
        const float numr = __fmaf_rn(e1, co1, -1.0f);
        const float numi = e1 * s1;
        const float tr = c0 * numr - c1 * numi;
        const float ti = c0 * numi + c1 * numr;
        const float inv = 2.0f / (are * are + aim * aim);
        const float csr = (ti * aim - tr * are) * inv;
        const float csi = -(ti * are + tr * aim) * inv;

        // step multiplier w = exp(LSTEP * dtA); |dim*LSTEP| <= ~160 rad
        const float m16 = __expf(dre * (float)LSTEP);
        const float p16 = red2pi_f(dim * (float)LSTEP);
        float s16, c16; __sincosf(p16, &s16, &c16);
        const float wr = m16 * c16;
        const float wi = m16 * s16;

        const float b = __fmaf_rn(wr, wr, wi * wi);  // |w|^2

        // base phase for this segment (the ONE fp64 reduction)
        const float pb = red2pi((double)dim * (double)l_base);

        stA[n] = make_float4(csr, csi, dre, dim);
        stB[n] = make_float4(pb, wr, wi, 1.0f / b);
        swc[n >> 4][0][n & 15] = 2.0f * wr;          // a
        swc[n >> 4][1][n & 15] = -b;                 // -b
    }
    __syncwarp();

    // ---------- Phase B: per-thread state init from staged values ----------
    u64 xc[NPAIR], xo[NPAIR];        // x(l0), x(l0 - LSTEP)
    const float lhf = (float)lhalf;
    const float l0f = (float)l0;

    #pragma unroll
    for (int p = 0; p < NPAIR; ++p) {
        float xcv[2], xov[2];
        #pragma unroll
        for (int k = 0; k < 2; ++k) {
            const int n = half * 16 + 2 * p + k;
            const float4 A4 = stA[n];
            const float4 B4 = stB[n];

            const float mag = __expf(A4.z * l0f);
            const float ph  = red2pi_f(__fmaf_rn(A4.w, lhf, B4.x));
            float sp, cp; __sincosf(ph, &sp, &cp);
            const float er = mag * cp, ei = mag * sp;
            const float y0r = A4.x * er - A4.y * ei;
            const float y0i = A4.x * ei + A4.y * er;

            xcv[k] = y0r;
            // x(l0 - LSTEP) = Re(y0 * conj(w)) / |w|^2
            xov[k] = __fmaf_rn(y0r, B4.y, y0i * B4.z) * B4.w;
        }
        F2PACK(xc[p], xcv[0], xcv[1]);
        F2PACK(xo[p], xov[0], xov[1]);
    }

    unsigned swb;
    asm("{ .reg .u64 t; cvta.to.shared.u64 t, %1; cvt.u32.u64 %0, t; }"
        : "=r"(swb) : "l"(&swc[half][0][0]));

    float* out = K + (size_t)h * L + l_base + lhalf;

    // iters is even (64): ping-pong the two buffers, no register copies.
    #pragma unroll 1
    for (int it = 0; it < iters; it += 2) {
        BODY(xc, xo);   // outputs x(l), xo <- x(l+LSTEP)
        BODY(xo, xc);   // outputs x(l+LSTEP), xc <- x(l+2*LSTEP)
    }
}

extern "C" void kernel_launch(void* const* d_in, const int* in_sizes, int n_in,
                              void* d_out, int out_size) {
    const float* C          = (const float*)d_in[0];
    const float* log_dt     = (const float*)d_in[1];
    const float* log_A_real = (const float*)d_in[2];
    const float* A_imag     = (const float*)d_in[3];

    const int H = in_sizes[1];           // log_dt has H elements
    const int L = out_size / H;          // K is (H, L)
    const int iters = L / (SEGS * LSTEP);

    s4d_kernel<<<H * SEGS, 32>>>(C, log_dt, log_A_real, A_imag,
                                 (float*)d_out, H, L, iters);
}